// round 3
// baseline (speedup 1.0000x reference)
#include <cuda_runtime.h>

#define THREADS 256
#define BLOCKS  1184   // 148 SMs * 8 blocks

// Self-cleaning global accumulator: starts 0 (static init); the last block of
// every launch writes the result to out and resets both back to 0, so every
// graph replay sees identical initial state. No separate zeroing kernel.
__device__ float        g_acc  = 0.0f;
__device__ unsigned int g_done = 0;

__global__ __launch_bounds__(THREADS)
void loss_synonymy_kernel(const float4* __restrict__ s1,
                          const float4* __restrict__ s2,
                          const float*  __restrict__ score,
                          float* __restrict__ out,
                          int B)
{
    const int lane   = threadIdx.x & 31;
    const int warp   = (blockIdx.x * THREADS + threadIdx.x) >> 5;
    const int nwarps = (gridDim.x * THREADS) >> 5;

    float acc = 0.0f;

    int row = warp;
    // 2 rows per iteration: 4 independent 128-bit loads issued up front
    // before any of the dependent shfl/tanh chains -> higher per-warp MLP.
    for (; row + nwarps < B; row += 2 * nwarps) {
        const int  row2  = row + nwarps;
        const long base1 = (long)row  * 32 + lane;
        const long base2 = (long)row2 * 32 + lane;

        float4 a1 = __ldg(&s1[base1]);
        float4 b1 = __ldg(&s2[base1]);
        float4 a2 = __ldg(&s1[base2]);
        float4 b2 = __ldg(&s2[base2]);
        float  sc1 = __ldg(&score[row]);
        float  sc2 = __ldg(&score[row2]);

        float dx1 = a1.x - b1.x, dy1 = a1.y - b1.y, dz1 = a1.z - b1.z, dw1 = a1.w - b1.w;
        float dx2 = a2.x - b2.x, dy2 = a2.y - b2.y, dz2 = a2.z - b2.z, dw2 = a2.w - b2.w;
        float ss1 = dx1*dx1 + dy1*dy1 + dz1*dz1 + dw1*dw1;
        float ss2 = dx2*dx2 + dy2*dy2 + dz2*dz2 + dw2*dw2;

        #pragma unroll
        for (int off = 16; off > 0; off >>= 1) {
            ss1 += __shfl_xor_sync(0xffffffffu, ss1, off);
            ss2 += __shfl_xor_sync(0xffffffffu, ss2, off);
        }

        float t1 = tanhf(sqrtf(ss1));
        float t2 = tanhf(sqrtf(ss2));
        float e1 = (sc1 >= 0.6f) ? (1.0f - t1) : (1.0f + t1);
        float e2 = (sc2 >= 0.6f) ? (1.0f - t2) : (1.0f + t2);
        acc += fmaxf(e1, 0.0f) + fmaxf(e2, 0.0f);
    }
    // tail: at most one remaining row for this warp
    if (row < B) {
        const long base = (long)row * 32 + lane;
        float4 a = __ldg(&s1[base]);
        float4 b = __ldg(&s2[base]);
        float dx = a.x - b.x, dy = a.y - b.y, dz = a.z - b.z, dw = a.w - b.w;
        float ss = dx*dx + dy*dy + dz*dz + dw*dw;
        #pragma unroll
        for (int off = 16; off > 0; off >>= 1)
            ss += __shfl_xor_sync(0xffffffffu, ss, off);
        float t  = tanhf(sqrtf(ss));
        float sc = __ldg(&score[row]);
        float e  = (sc >= 0.6f) ? (1.0f - t) : (1.0f + t);
        acc += fmaxf(e, 0.0f);
    }

    // acc is lane-uniform after the all-reduce math; reduce warps in the block.
    __shared__ float warp_sums[THREADS / 32];
    if (lane == 0) warp_sums[threadIdx.x >> 5] = acc;
    __syncthreads();

    if (threadIdx.x == 0) {
        float v = 0.0f;
        #pragma unroll
        for (int i = 0; i < THREADS / 32; i++) v += warp_sums[i];
        atomicAdd(&g_acc, v);
        __threadfence();
        unsigned int ticket = atomicAdd(&g_done, 1u);
        if (ticket == gridDim.x - 1) {
            // last block: publish result and reset state for the next replay
            out[0] = g_acc;
            g_acc  = 0.0f;
            g_done = 0;
        }
    }
}

extern "C" void kernel_launch(void* const* d_in, const int* in_sizes, int n_in,
                              void* d_out, int out_size)
{
    const float4* s1    = (const float4*)d_in[0];
    const float4* s2    = (const float4*)d_in[1];
    const float*  score = (const float*)d_in[2];
    float* out = (float*)d_out;

    const int B = in_sizes[2];  // synonymy_score has B elements

    loss_synonymy_kernel<<<BLOCKS, THREADS>>>(s1, s2, score, out, B);
}

// round 5
// speedup vs baseline: 1.0379x; 1.0379x over previous
#include <cuda_runtime.h>

#define THREADS 256
#define BLOCKS  1184   // 148 SMs * 8 blocks

// Self-cleaning global accumulator: starts 0 (static init); the last block of
// every launch publishes to out and resets state, so every graph replay sees
// identical initial conditions. No separate zeroing kernel launch.
__device__ float        g_acc  = 0.0f;
__device__ unsigned int g_done = 0;

__global__ __launch_bounds__(THREADS)
void loss_synonymy_kernel(const float4* __restrict__ s1,
                          const float4* __restrict__ s2,
                          const float*  __restrict__ score,
                          float* __restrict__ out,
                          int B)
{
    const int lane   = threadIdx.x & 31;
    const int warp   = (blockIdx.x * THREADS + threadIdx.x) >> 5;
    const int nwarps = (gridDim.x * THREADS) >> 5;

    float acc = 0.0f;

    // R1 body: one row per iteration, dense warp-per-row sweep (measured
    // DRAM=90%). Streaming loads (__ldcs): each byte is touched once.
    for (int row = warp; row < B; row += nwarps) {
        const long base = (long)row * 32 + lane;  // 32 float4 per row (D=128)
        float4 a = __ldcs(&s1[base]);
        float4 b = __ldcs(&s2[base]);

        float dx = a.x - b.x;
        float dy = a.y - b.y;
        float dz = a.z - b.z;
        float dw = a.w - b.w;
        float ss = dx*dx + dy*dy + dz*dz + dw*dw;

        // warp all-reduce of sum of squares
        #pragma unroll
        for (int off = 16; off > 0; off >>= 1)
            ss += __shfl_xor_sync(0xffffffffu, ss, off);

        float t  = tanhf(sqrtf(ss));
        float sc = __ldg(&score[row]);  // uniform across warp
        float e  = (sc >= 0.6f) ? (1.0f - t) : (1.0f + t);
        acc += fmaxf(e, 0.0f);
    }

    // acc is lane-uniform after the all-reduce math; reduce warps in block.
    __shared__ float warp_sums[THREADS / 32];
    if (lane == 0) warp_sums[threadIdx.x >> 5] = acc;
    __syncthreads();

    if (threadIdx.x == 0) {
        float v = 0.0f;
        #pragma unroll
        for (int i = 0; i < THREADS / 32; i++) v += warp_sums[i];
        atomicAdd(&g_acc, v);
        __threadfence();
        unsigned int ticket = atomicAdd(&g_done, 1u);
        if (ticket == gridDim.x - 1) {
            out[0] = g_acc;   // publish
            g_acc  = 0.0f;    // reset for next replay
            g_done = 0;
        }
    }
}

extern "C" void kernel_launch(void* const* d_in, const int* in_sizes, int n_in,
                              void* d_out, int out_size)
{
    const float4* s1    = (const float4*)d_in[0];
    const float4* s2    = (const float4*)d_in[1];
    const float*  score = (const float*)d_in[2];
    float* out = (float*)d_out;

    const int B = in_sizes[2];  // synonymy_score has B elements

    loss_synonymy_kernel<<<BLOCKS, THREADS>>>(s1, s2, score, out, B);
}